// round 13
// baseline (speedup 1.0000x reference)
#include <cuda_runtime.h>
#include <cuda_bf16.h>

// DTW min-plus DP, N=65536 rows, K=512 cols, output ac[i][511].
//
// 4-CTA column-block pipeline. CTA c owns global columns [128c, 128c+128).
// Inside each CTA: band-rotation wavefront (128 threads, bands of 32 rows;
// left column lives in registers; up-carry moves p-1 -> p via shfl, warp ring
// via smem). CTA c-1 streams its right-edge column to CTA c through global
// memory, gated by per-band release/acquire flags (st.release.gpu /
// ld.acquire.gpu + nanosleep backoff). Boundary + x data for the next chunk
// are prefetched 4 supersteps early so L2 latency overlaps compute.

#define NROWS   65536
#define KCOLS   512
#define RB      32
#define CTAS    4
#define TPB     128
#define LCOLS   (KCOLS / CTAS)          // 128
#define NBANDS  (NROWS / RB)            // 2048
#define CHUNKS  (NBANDS / TPB)          // 16
#define TOTALPH (LCOLS * CHUNKS)        // 2048 active phases per thread
#define NSTEPS  (TPB - 1 + TOTALPH)     // 2175 supersteps per CTA
#define PREF_J  (LCOLS - 4)             // prefetch point inside a chunk

__device__ float    g_bound[CTAS - 1][NROWS];
__device__ unsigned g_flag[CTAS - 1][NBANDS];

__global__ void init_flags_kernel()
{
    int i = blockIdx.x * blockDim.x + threadIdx.x;
    if (i < (CTAS - 1) * NBANDS)
        ((unsigned*)g_flag)[i] = 0u;
}

__device__ __forceinline__ unsigned ld_acq(const unsigned* p)
{
    unsigned v;
    asm volatile("ld.acquire.gpu.global.b32 %0, [%1];"
                 : "=r"(v) : "l"(p) : "memory");
    return v;
}

__device__ __forceinline__ void st_rel(unsigned* p, unsigned v)
{
    asm volatile("st.release.gpu.global.b32 [%0], %1;"
                 :: "l"(p), "r"(v) : "memory");
}

__device__ __forceinline__ void wait_flag(const unsigned* p)
{
    while (!ld_acq(p)) __nanosleep(32);
}

__global__ void __launch_bounds__(TPB, 1)
dtw_pipe_kernel(const float* __restrict__ x, const float* __restrict__ ker,
                float* __restrict__ out)
{
    const int c = blockIdx.x;
    __shared__ float sk[LCOLS];
    __shared__ float sbuf[2][TPB / 32];

    const int p    = threadIdx.x;
    const int lane = p & 31;
    const int warp = p >> 5;
    const float INF = __int_as_float(0x7f800000);

    sk[p] = ker[c * LCOLS + p];
    if (lane == 31) { sbuf[0][warp] = INF; sbuf[1][warp] = INF; }
    __syncthreads();

    float V[RB];          // current column values (left col next superstep)
    float xv[RB];         // this chunk's input values
    float xst[RB];        // staged next-chunk inputs
    float bst[RB + 1];    // staged next-chunk boundary: [0]=diag, [1..32]=left
    float diagc = INF;
    float alast = INF;

    int phase = -p;       // chunk k = phase>>7, local column jl = phase&127

    for (int t = 0; t < NSTEPS; ++t, ++phase) {
        float nb = __shfl_up_sync(0xffffffffu, alast, 1);
        if (lane == 0) nb = sbuf[t & 1][(warp + 3) & 3];

        if (phase >= 0 && phase < TOTALPH) {
            const int jl = phase & (LCOLS - 1);
            const int k  = phase >> 7;

            if (jl == 0) {
                const int band = p + TPB * k;
                const int i0   = band * RB;
                if (k == 0) {
                    // pipeline fill: direct (blocking) loads
                    const float4* xp = reinterpret_cast<const float4*>(x + i0);
#pragma unroll
                    for (int q = 0; q < RB / 4; ++q) {
                        float4 v = xp[q];
                        xv[4*q+0] = v.x; xv[4*q+1] = v.y;
                        xv[4*q+2] = v.z; xv[4*q+3] = v.w;
                    }
                    if (c > 0) {
                        wait_flag(&g_flag[c - 1][band]);
                        const float4* bp =
                            reinterpret_cast<const float4*>(&g_bound[c - 1][i0]);
#pragma unroll
                        for (int q = 0; q < RB / 4; ++q) {
                            float4 v = __ldcg(bp + q);
                            V[4*q+0] = v.x; V[4*q+1] = v.y;
                            V[4*q+2] = v.z; V[4*q+3] = v.w;
                        }
                        diagc = (i0 == 0) ? INF : __ldcg(&g_bound[c - 1][i0 - 1]);
                    } else {
#pragma unroll
                        for (int r = 0; r < RB; ++r) V[r] = INF;
                        diagc = (p == 0) ? 0.0f : INF;  // virtual diag for (0,0)
                    }
                } else {
                    // staged at PREF_J of the previous chunk
#pragma unroll
                    for (int r = 0; r < RB; ++r) xv[r] = xst[r];
                    if (c > 0) {
#pragma unroll
                        for (int r = 0; r < RB; ++r) V[r] = bst[r + 1];
                        diagc = bst[0];
                    } else {
#pragma unroll
                        for (int r = 0; r < RB; ++r) V[r] = INF;
                        diagc = INF;
                    }
                }
            }

            // up-carry ac[i0-1][gj]; +inf above the very first band
            const float upv = (p == 0 && phase < LCOLS) ? INF : nb;
            const float kj  = sk[jl];

            float a     = upv;
            float prevL = diagc;
#pragma unroll
            for (int r = 0; r < RB; ++r) {
                const float curL = V[r];
                const float u    = kj - xv[r];
                a = fminf(a, fminf(curL, prevL));
                a = fmaf(u, u, a);
                prevL = curL;
                V[r] = a;
            }
            diagc = upv;
            alast = a;

            if (jl == LCOLS - 1) {
                const int band = p + TPB * k;
                const int i0   = band * RB;
                if (c == CTAS - 1) {
                    float4* op = reinterpret_cast<float4*>(out + i0);
#pragma unroll
                    for (int q = 0; q < RB / 4; ++q)
                        op[q] = make_float4(V[4*q+0], V[4*q+1],
                                            V[4*q+2], V[4*q+3]);
                } else {
                    float4* bp = reinterpret_cast<float4*>(&g_bound[c][i0]);
#pragma unroll
                    for (int q = 0; q < RB / 4; ++q)
                        __stcg(bp + q, make_float4(V[4*q+0], V[4*q+1],
                                                   V[4*q+2], V[4*q+3]));
                    st_rel(&g_flag[c][band], 1u);  // release: data visible first
                }
            }

            if (jl == PREF_J && k + 1 < CHUNKS) {
                const int band_n = p + TPB * (k + 1);
                const int i0n    = band_n * RB;
                const float4* xp = reinterpret_cast<const float4*>(x + i0n);
#pragma unroll
                for (int q = 0; q < RB / 4; ++q) {
                    float4 v = xp[q];
                    xst[4*q+0] = v.x; xst[4*q+1] = v.y;
                    xst[4*q+2] = v.z; xst[4*q+3] = v.w;
                }
                if (c > 0) {
                    wait_flag(&g_flag[c - 1][band_n]);   // implies band_n-1 too
                    const float4* bp =
                        reinterpret_cast<const float4*>(&g_bound[c - 1][i0n]);
#pragma unroll
                    for (int q = 0; q < RB / 4; ++q) {
                        float4 v = __ldcg(bp + q);
                        bst[1+4*q+0] = v.x; bst[1+4*q+1] = v.y;
                        bst[1+4*q+2] = v.z; bst[1+4*q+3] = v.w;
                    }
                    // i0n >= TPB*RB > 0 here, so i0n-1 is valid
                    bst[0] = __ldcg(&g_bound[c - 1][i0n - 1]);
                }
            }
        }

        if (lane == 31) sbuf[(t + 1) & 1][warp] = alast;
        __syncthreads();
    }
}

extern "C" void kernel_launch(void* const* d_in, const int* in_sizes, int n_in,
                              void* d_out, int out_size)
{
    const float* x   = (const float*)d_in[0];   // input, 65536
    const float* ker = (const float*)d_in[1];   // kernel, 512
    float* out = (float*)d_out;                 // 65536
    (void)in_sizes; (void)n_in; (void)out_size;

    init_flags_kernel<<<((CTAS - 1) * NBANDS + 255) / 256, 256>>>();
    dtw_pipe_kernel<<<CTAS, TPB>>>(x, ker, out);
}

// round 14
// speedup vs baseline: 1.1996x; 1.1996x over previous
#include <cuda_runtime.h>
#include <cuda_bf16.h>
#include <cstdint>

// DTW min-plus DP, N=65536 rows, K=512 cols, output ac[i][511].
//
// 4-CTA CLUSTER column pipeline. CTA c owns global columns [128c, 128c+128).
// Band-rotation wavefront inside each CTA (128 threads, bands of 32 rows;
// left column in registers; up-carry p-1 -> p via shfl, warp ring via smem).
// Boundary handoff CTA c -> c+1 goes through the CONSUMER's shared memory
// (DSMEM): producer st.shared::cluster the 32-value column + st.release.cluster
// a per-slot flag; consumer ld.acquire.cluster polls its OWN smem (~38cy, not
// ~300cy L2) and stages the data 4 supersteps before use. 256-slot ring with a
// monotone ack cell for backpressure (never hot: natural lag ~131 << 256).

#define NROWS   65536
#define KCOLS   512
#define RB      32
#define CTAS    4
#define TPB     128
#define LCOLS   (KCOLS / CTAS)          // 128
#define NBANDS  (NROWS / RB)            // 2048
#define CHUNKS  (NBANDS / TPB)          // 16
#define TOTALPH (LCOLS * CHUNKS)        // 2048 active phases per thread
#define NSTEPS  (TOTALPH + TPB - 1)     // 2175 supersteps
#define PREF_J  (LCOLS - 4)             // staging point inside a chunk
#define SLOTS   256                      // boundary ring slots (32KB)

__device__ __forceinline__ uint32_t smem_u32(const void* p) {
    return (uint32_t)__cvta_generic_to_shared(p);
}
__device__ __forceinline__ uint32_t mapa_rank(uint32_t addr, uint32_t rank) {
    uint32_t r;
    asm("mapa.shared::cluster.u32 %0, %1, %2;" : "=r"(r) : "r"(addr), "r"(rank));
    return r;
}
__device__ __forceinline__ void sts_cluster_v4(uint32_t addr, float4 v) {
    asm volatile("st.shared::cluster.v4.f32 [%0], {%1,%2,%3,%4};"
                 :: "r"(addr), "f"(v.x), "f"(v.y), "f"(v.z), "f"(v.w) : "memory");
}
__device__ __forceinline__ void st_rel_cluster(uint32_t addr, unsigned v) {
    asm volatile("st.release.cluster.shared::cluster.u32 [%0], %1;"
                 :: "r"(addr), "r"(v) : "memory");
}
__device__ __forceinline__ unsigned ld_acq_cluster(uint32_t addr) {
    unsigned v;
    asm volatile("ld.acquire.cluster.shared::cluster.u32 %0, [%1];"
                 : "=r"(v) : "r"(addr) : "memory");
    return v;
}
__device__ __forceinline__ void st_rlx_cluster(uint32_t addr, unsigned v) {
    asm volatile("st.relaxed.cluster.shared::cluster.u32 [%0], %1;"
                 :: "r"(addr), "r"(v) : "memory");
}
__device__ __forceinline__ unsigned ld_rlx_cluster(uint32_t addr) {
    unsigned v;
    asm volatile("ld.relaxed.cluster.shared::cluster.u32 %0, [%1];"
                 : "=r"(v) : "r"(addr) : "memory");
    return v;
}
__device__ __forceinline__ void cluster_sync_() {
    asm volatile("barrier.cluster.arrive.aligned;" ::: "memory");
    asm volatile("barrier.cluster.wait.aligned;" ::: "memory");
}

__global__ void __launch_bounds__(TPB, 1) __cluster_dims__(CTAS, 1, 1)
dtw_cluster_kernel(const float* __restrict__ x, const float* __restrict__ ker,
                   float* __restrict__ out)
{
    __shared__ float    sk[LCOLS];
    __shared__ float    sbuf[2][TPB / 32];
    __shared__ float    ring[SLOTS][RB];     // boundary slots, written by producer CTA
    __shared__ unsigned rflag[SLOTS];        // flag[s] = band+1 once slot holds that band
    __shared__ unsigned ackcell;             // monotone: written remotely by downstream CTA

    const int c    = blockIdx.x;             // cluster rank == column block
    const int p    = threadIdx.x;
    const int lane = p & 31;
    const int warp = p >> 5;
    const float INF = __int_as_float(0x7f800000);

    sk[p] = ker[c * LCOLS + p];
    for (int s = p; s < SLOTS; s += TPB) rflag[s] = 0u;
    if (p == 0) ackcell = 0u;
    if (lane == 31) { sbuf[0][warp] = INF; sbuf[1][warp] = INF; }
    __syncthreads();
    cluster_sync_();   // peers' smem initialized before any remote traffic

    // cluster-window addresses
    const uint32_t ring_loc = smem_u32(&ring[0][0]);
    const uint32_t flag_loc = smem_u32(&rflag[0]);
    const uint32_t ack_loc  = smem_u32(&ackcell);
    const uint32_t myflag   = mapa_rank(flag_loc, (uint32_t)c);
    const uint32_t myack    = mapa_rank(ack_loc,  (uint32_t)c);
    uint32_t ring_next = 0, flag_next = 0, ack_prev = 0;
    if (c + 1 < CTAS) {
        ring_next = mapa_rank(ring_loc, (uint32_t)(c + 1));
        flag_next = mapa_rank(flag_loc, (uint32_t)(c + 1));
    }
    if (c > 0) ack_prev = mapa_rank(ack_loc, (uint32_t)(c - 1));

    float V[RB];          // current column values (left col next superstep)
    float xv[RB];         // this chunk's input values
    float xst[RB];        // staged next-chunk inputs
    float bst[RB + 1];    // staged next-chunk boundary: [0]=diag, [1..32]=left
    float diagc = INF;
    float alast = INF;

    // preload chunk-0 inputs (consumed starting at t == p; latency hidden by stagger)
    {
        const float4* xp = reinterpret_cast<const float4*>(x + p * RB);
#pragma unroll
        for (int q = 0; q < RB / 4; ++q) {
            float4 v = xp[q];
            xv[4*q+0] = v.x; xv[4*q+1] = v.y;
            xv[4*q+2] = v.z; xv[4*q+3] = v.w;
        }
    }

    int phase = -p;       // chunk k = phase>>7, local column jl = phase&127

    for (int t = 0; t < NSTEPS; ++t, ++phase) {
        float nb = __shfl_up_sync(0xffffffffu, alast, 1);
        if (lane == 0) nb = sbuf[t & 1][(warp + 3) & 3];

        if (phase >= 0 && phase < TOTALPH) {
            const int jl   = phase & (LCOLS - 1);
            const int k    = phase >> 7;
            const int band = p + (k << 7);

            if (jl == 0) {
                if (k == 0) {
                    // xv already preloaded; fetch boundary (cold path, fills lag)
                    if (c > 0) {
                        const int s = band;  // band < 128 < SLOTS
                        while ((int)ld_acq_cluster(myflag + 4u * s) < band + 1) {}
#pragma unroll
                        for (int q = 0; q < RB / 4; ++q) {
                            float4 v = *reinterpret_cast<const float4*>(&ring[s][4*q]);
                            V[4*q+0] = v.x; V[4*q+1] = v.y;
                            V[4*q+2] = v.z; V[4*q+3] = v.w;
                        }
                        diagc = (band == 0) ? INF : ring[band - 1][31];
                        st_rlx_cluster(ack_prev, (unsigned)(band + 1));
                    } else {
#pragma unroll
                        for (int r = 0; r < RB; ++r) V[r] = INF;
                        diagc = (p == 0) ? 0.0f : INF;  // virtual diag for (0,0)
                    }
                } else {
                    // staged at PREF_J of the previous chunk
#pragma unroll
                    for (int r = 0; r < RB; ++r) xv[r] = xst[r];
                    if (c > 0) {
#pragma unroll
                        for (int r = 0; r < RB; ++r) V[r] = bst[r + 1];
                        diagc = bst[0];
                    } else {
#pragma unroll
                        for (int r = 0; r < RB; ++r) V[r] = INF;
                        diagc = INF;
                    }
                }
            }

            // up-carry ac[i0-1][gj]; +inf above the very first band
            const float upv = (p == 0 && phase < LCOLS) ? INF : nb;
            const float kj  = sk[jl];

            float a     = upv;
            float prevL = diagc;
#pragma unroll
            for (int r = 0; r < RB; ++r) {
                const float curL = V[r];
                const float u    = kj - xv[r];
                a = fminf(a, fminf(curL, prevL));
                a = fmaf(u, u, a);
                prevL = curL;
                V[r] = a;
            }
            diagc = upv;
            alast = a;

            if (jl == LCOLS - 1) {
                if (c == CTAS - 1) {
                    float4* op = reinterpret_cast<float4*>(out + band * RB);
#pragma unroll
                    for (int q = 0; q < RB / 4; ++q)
                        op[q] = make_float4(V[4*q+0], V[4*q+1],
                                            V[4*q+2], V[4*q+3]);
                } else {
                    const int s = band & (SLOTS - 1);
                    if (band >= SLOTS - 1) {
                        // slot's previous occupant (band-SLOTS) last read as the
                        // diag of band-SLOTS+1, acked with value band-SLOTS+2
                        while ((int)ld_rlx_cluster(myack) < band - SLOTS + 2) {}
                    }
                    const uint32_t dst = ring_next + (uint32_t)s * (RB * 4);
#pragma unroll
                    for (int q = 0; q < RB / 4; ++q)
                        sts_cluster_v4(dst + 16u * q,
                                       make_float4(V[4*q+0], V[4*q+1],
                                                   V[4*q+2], V[4*q+3]));
                    st_rel_cluster(flag_next + 4u * s, (unsigned)(band + 1));
                }
            }

            if (jl == PREF_J && k + 1 < CHUNKS) {
                const int band_n = band + TPB;
                const float4* xp = reinterpret_cast<const float4*>(x + band_n * RB);
#pragma unroll
                for (int q = 0; q < RB / 4; ++q) {
                    float4 v = xp[q];
                    xst[4*q+0] = v.x; xst[4*q+1] = v.y;
                    xst[4*q+2] = v.z; xst[4*q+3] = v.w;
                }
                if (c > 0) {
                    const int s = band_n & (SLOTS - 1);
                    while ((int)ld_acq_cluster(myflag + 4u * s) < band_n + 1) {}
#pragma unroll
                    for (int q = 0; q < RB / 4; ++q) {
                        float4 v = *reinterpret_cast<const float4*>(&ring[s][4*q]);
                        bst[1+4*q+0] = v.x; bst[1+4*q+1] = v.y;
                        bst[1+4*q+2] = v.z; bst[1+4*q+3] = v.w;
                    }
                    // band_n >= 128 > 0, so band_n-1 is valid; its data is
                    // covered by flag[band_n] via producer-side barriers
                    bst[0] = ring[(band_n - 1) & (SLOTS - 1)][31];
                    st_rlx_cluster(ack_prev, (unsigned)(band_n + 1));
                }
            }
        }

        if (lane == 31) sbuf[(t + 1) & 1][warp] = alast;
        __syncthreads();
    }

    // no CTA may exit while peers can still write into its smem
    cluster_sync_();
}

extern "C" void kernel_launch(void* const* d_in, const int* in_sizes, int n_in,
                              void* d_out, int out_size)
{
    const float* x   = (const float*)d_in[0];   // input, 65536
    const float* ker = (const float*)d_in[1];   // kernel, 512
    float* out = (float*)d_out;                 // 65536
    (void)in_sizes; (void)n_in; (void)out_size;

    dtw_cluster_kernel<<<CTAS, TPB>>>(x, ker, out);
}

// round 15
// speedup vs baseline: 1.5594x; 1.2999x over previous
#include <cuda_runtime.h>
#include <cuda_bf16.h>

// DTW min-plus DP, N=65536 rows (input), K=512 cols (kernel).
// ac[i][j] = min(ac[i-1][j-1], ac[i-1][j], ac[i][j-1]) + (kernel[j]-input[i])^2
// boundary: row -1 and col -1 = +inf, except diag for (0,0) = 0.
// Output: ac[i][K-1] for all i.
//
// Single-CTA band-rotation wavefront (best geometry measured): thread p owns
// bands m = p + 512*k (32 rows each), sweeping columns 0..511 over consecutive
// supersteps. Left column lives in registers; the up-carry scalar moves
// p-1 -> p via one shfl per superstep (smem word at warp boundaries, ring
// warp15 -> warp0). NEW vs R6: next-chunk x values are staged into registers
// 16 supersteps before use (j==496), so the 8x LDG latency never lands on the
// barrier-critical lane at j==0.

#define NROWS   65536
#define KCOLS   512
#define RB      32
#define NBANDS  (NROWS / RB)          // 2048
#define NTHREADS 512
#define CHUNKS  (NBANDS / NTHREADS)   // 4
#define TOTALPH (KCOLS * CHUNKS)      // 2048 phases per thread
#define NSTEPS  (TOTALPH + NTHREADS - 1) // 2559 supersteps
#define PREF_J  (KCOLS - 16)          // x staging point (16 steps early)

__global__ void __launch_bounds__(NTHREADS, 1)
dtw_band_kernel(const float* __restrict__ x, const float* __restrict__ ker,
                float* __restrict__ out)
{
    __shared__ float sk[KCOLS];
    __shared__ float sbuf[2][NTHREADS / 32];

    const int p    = threadIdx.x;
    const int lane = p & 31;
    const int warp = p >> 5;
    const float INF = __int_as_float(0x7f800000);

    sk[p] = ker[p];
    if (lane == 31) { sbuf[0][warp] = INF; sbuf[1][warp] = INF; }
    __syncthreads();

    float V[RB];     // current column values (left col for next superstep)
    float xv[RB];    // this chunk's input values
    float xst[RB];   // staged next-chunk input values
    float diagc = INF;
    float alast = INF;

    // preload chunk-0 inputs (first consumed at t == p; stagger hides latency)
    {
        const float4* xp = reinterpret_cast<const float4*>(x + p * RB);
#pragma unroll
        for (int q = 0; q < RB / 4; ++q) {
            float4 v = xp[q];
            xv[4*q+0] = v.x; xv[4*q+1] = v.y;
            xv[4*q+2] = v.z; xv[4*q+3] = v.w;
        }
    }

    int phase = -p;   // chunk k = phase>>9, column j = phase&511

    for (int t = 0; t < NSTEPS; ++t, ++phase) {
        float nb = __shfl_up_sync(0xffffffffu, alast, 1);
        if (lane == 0) nb = sbuf[t & 1][(warp + 15) & 15];

        if (phase >= 0 && phase < TOTALPH) {
            const int j = phase & (KCOLS - 1);
            const int k = phase >> 9;

            if (j == 0) {
                if (k > 0) {   // staged 16 supersteps ago; scoreboard long drained
#pragma unroll
                    for (int r = 0; r < RB; ++r) xv[r] = xst[r];
                }
#pragma unroll
                for (int r = 0; r < RB; ++r) V[r] = INF;
                diagc = (p == 0 && k == 0) ? 0.0f : INF;  // virtual diag for (0,0)
            }

            // up-carry ac[i0-1][j]; +inf above the very first band
            const float upv = (p == 0 && phase < KCOLS) ? INF : nb;
            const float kj  = sk[j];

            float a     = upv;
            float prevL = diagc;
#pragma unroll
            for (int r = 0; r < RB; ++r) {
                const float curL = V[r];
                const float u    = kj - xv[r];
                a = fminf(a, fminf(curL, prevL));
                a = fmaf(u, u, a);
                prevL = curL;
                V[r] = a;
            }
            diagc = upv;
            alast = a;

            if (j == KCOLS - 1) {
                const int i0 = (p + (k << 9)) * RB;
                float4* op = reinterpret_cast<float4*>(out + i0);
#pragma unroll
                for (int q = 0; q < RB / 4; ++q)
                    op[q] = make_float4(V[4*q+0], V[4*q+1],
                                        V[4*q+2], V[4*q+3]);
            }

            if (j == PREF_J && k + 1 < CHUNKS) {
                const int i0n = (p + ((k + 1) << 9)) * RB;
                const float4* xp = reinterpret_cast<const float4*>(x + i0n);
#pragma unroll
                for (int q = 0; q < RB / 4; ++q) {
                    float4 v = xp[q];
                    xst[4*q+0] = v.x; xst[4*q+1] = v.y;
                    xst[4*q+2] = v.z; xst[4*q+3] = v.w;
                }
            }
        }

        if (lane == 31) sbuf[(t + 1) & 1][warp] = alast;
        __syncthreads();
    }
}

extern "C" void kernel_launch(void* const* d_in, const int* in_sizes, int n_in,
                              void* d_out, int out_size)
{
    const float* x   = (const float*)d_in[0];   // input, 65536
    const float* ker = (const float*)d_in[1];   // kernel, 512
    float* out = (float*)d_out;                 // 65536
    (void)in_sizes; (void)n_in; (void)out_size;

    dtw_band_kernel<<<1, NTHREADS>>>(x, ker, out);
}

// round 16
// speedup vs baseline: 2.0929x; 1.3421x over previous
#include <cuda_runtime.h>
#include <cuda_bf16.h>
#include <cstdint>

// DTW min-plus DP, N=65536 rows (input), K=512 cols (kernel).
// ac[i][j] = min(ac[i-1][j-1], ac[i-1][j], ac[i][j-1]) + (kernel[j]-input[i])^2
// boundary: row -1 and col -1 = +inf, except diag for (0,0) = 0.
// Output: ac[i][K-1] for all i.
//
// Single-CTA band-rotation wavefront (R6 geometry, best measured): thread p
// owns bands m = p + 512*k (32 rows each), sweeping columns 0..511 across
// supersteps. Left column in registers; up-carry p-1 -> p via shfl, warp ring
// via smem. NEW: next-chunk x is staged via cp.async into a 32-slot x 128B
// smem ring 16 supersteps early (j==496), so the consuming thread at j==0
// does 8 cheap LDS instead of 8 blocking LDGs -- zero register cost (R15's
// register-staging spilled at 128 regs and regressed).

#define NROWS    65536
#define KCOLS    512
#define RB       32
#define NBANDS   (NROWS / RB)           // 2048
#define NTHREADS 512
#define CHUNKS   (NBANDS / NTHREADS)    // 4
#define TOTALPH  (KCOLS * CHUNKS)       // 2048 phases per thread
#define NSTEPS   (TOTALPH + NTHREADS - 1) // 2559 supersteps
#define PREF_J   (KCOLS - 16)           // staging point: 16 supersteps early
#define XSLOTS   32                     // staging ring slots (only <=16 in flight)

__device__ __forceinline__ void cp_async16(uint32_t dst_smem, const void* src) {
    asm volatile("cp.async.ca.shared.global [%0], [%1], 16;"
                 :: "r"(dst_smem), "l"(src) : "memory");
}
__device__ __forceinline__ void cp_async_commit() {
    asm volatile("cp.async.commit_group;" ::: "memory");
}
__device__ __forceinline__ void cp_async_wait0() {
    asm volatile("cp.async.wait_group 0;" ::: "memory");
}

__global__ void __launch_bounds__(NTHREADS, 1)
dtw_band_kernel(const float* __restrict__ x, const float* __restrict__ ker,
                float* __restrict__ out)
{
    __shared__ float sk[KCOLS];
    __shared__ float sbuf[2][NTHREADS / 32];
    __shared__ __align__(16) float sxst[XSLOTS][RB];   // 4KB staging ring

    const int p    = threadIdx.x;
    const int lane = p & 31;
    const int warp = p >> 5;
    const float INF = __int_as_float(0x7f800000);

    sk[p] = ker[p];
    if (lane == 31) { sbuf[0][warp] = INF; sbuf[1][warp] = INF; }
    __syncthreads();

    float V[RB];     // current column values (left col for next superstep)
    float xv[RB];    // this chunk's input values
    float diagc = INF;
    float alast = INF;

    // preload chunk-0 inputs directly into xv (first used at t == p; the
    // thread stagger hides this latency for all but thread 0)
    {
        const float4* xp = reinterpret_cast<const float4*>(x + p * RB);
#pragma unroll
        for (int q = 0; q < RB / 4; ++q) {
            float4 v = xp[q];
            xv[4*q+0] = v.x; xv[4*q+1] = v.y;
            xv[4*q+2] = v.z; xv[4*q+3] = v.w;
        }
    }

    const uint32_t myslot =
        (uint32_t)__cvta_generic_to_shared(&sxst[p & (XSLOTS - 1)][0]);

    int phase = -p;   // chunk k = phase>>9, column j = phase&511

    for (int t = 0; t < NSTEPS; ++t, ++phase) {
        float nb = __shfl_up_sync(0xffffffffu, alast, 1);
        if (lane == 0) nb = sbuf[t & 1][(warp + 15) & 15];

        if (phase >= 0 && phase < TOTALPH) {
            const int j = phase & (KCOLS - 1);
            const int k = phase >> 9;

            if (j == 0) {
                if (k > 0) {
                    // staged by cp.async 16 supersteps ago; wait is free
                    cp_async_wait0();
                    const float4* sp =
                        reinterpret_cast<const float4*>(&sxst[p & (XSLOTS - 1)][0]);
#pragma unroll
                    for (int q = 0; q < RB / 4; ++q) {
                        float4 v = sp[q];
                        xv[4*q+0] = v.x; xv[4*q+1] = v.y;
                        xv[4*q+2] = v.z; xv[4*q+3] = v.w;
                    }
                }
#pragma unroll
                for (int r = 0; r < RB; ++r) V[r] = INF;
                diagc = (p == 0 && k == 0) ? 0.0f : INF;  // virtual diag for (0,0)
            }

            // up-carry ac[i0-1][j]; +inf above the very first band
            const float upv = (p == 0 && phase < KCOLS) ? INF : nb;
            const float kj  = sk[j];

            float a     = upv;
            float prevL = diagc;
#pragma unroll
            for (int r = 0; r < RB; ++r) {
                const float curL = V[r];
                const float u    = kj - xv[r];
                a = fminf(a, fminf(curL, prevL));
                a = fmaf(u, u, a);
                prevL = curL;
                V[r] = a;
            }
            diagc = upv;
            alast = a;

            if (j == KCOLS - 1) {
                const int i0 = (p + (k << 9)) * RB;
                float4* op = reinterpret_cast<float4*>(out + i0);
#pragma unroll
                for (int q = 0; q < RB / 4; ++q)
                    op[q] = make_float4(V[4*q+0], V[4*q+1],
                                        V[4*q+2], V[4*q+3]);
            }

            if (j == PREF_J && k + 1 < CHUNKS) {
                // fire-and-forget: 8x 16B cp.async into my ring slot
                const float* src = x + (p + ((k + 1) << 9)) * RB;
#pragma unroll
                for (int q = 0; q < RB / 4; ++q)
                    cp_async16(myslot + 16u * q, src + 4 * q);
                cp_async_commit();
            }
        }

        if (lane == 31) sbuf[(t + 1) & 1][warp] = alast;
        __syncthreads();
    }
}

extern "C" void kernel_launch(void* const* d_in, const int* in_sizes, int n_in,
                              void* d_out, int out_size)
{
    const float* x   = (const float*)d_in[0];   // input, 65536
    const float* ker = (const float*)d_in[1];   // kernel, 512
    float* out = (float*)d_out;                 // 65536
    (void)in_sizes; (void)n_in; (void)out_size;

    dtw_band_kernel<<<1, NTHREADS>>>(x, ker, out);
}